// round 4
// baseline (speedup 1.0000x reference)
#include <cuda_runtime.h>

#define MAXR 100.0f

__device__ __forceinline__ float tanh_fast(float x) {
    float r;
    asm("tanh.approx.f32 %0, %1;" : "=f"(r) : "f"(x));
    return r;
}

// ---------------------------------------------------------------------------
// Fused kernel, per block = 8 consecutive same-row pixels.
// Key fact: logit_j = -|a|*mean_i(|d|*tanh(|a d|)) <= 0, clipped at -100.
// For most pixels ALL logits pre-clip below -100 -> softmax exactly uniform
// -> out = mean_c(x). Two conservative screens (exact math bounds, using
// s*(1-tanh s) <= 0.30) detect this without evaluating any tanh:
//   C0: |a|*(|b|*mean|x| - max|x|) >= 101           (O(C), reverse triangle)
//   C1: min_j Sum_i|z_ij| / 64    >= 100.6          (O(C^2), fma-pipe only)
// Pixels failing both run the exact tanh path (identical to prior kernel).
// ---------------------------------------------------------------------------
__global__ __launch_bounds__(256) void dsf_fused_kernel(
    const float* __restrict__ x,
    const float* __restrict__ wgt,
    const float* __restrict__ bias,
    float* __restrict__ out) {

    __shared__ float tile[64][31];  // [c][r*10+cc], stride 31 => conflict-free
    __shared__ float sw[1152];      // conv weights [2][64][3][3]
    __shared__ float su[8][64];     // per-pixel u_i = alpha*beta*x_i

    int tid = threadIdx.x;
    int p0  = blockIdx.x * 8;
    int b   = p0 >> 12;
    int hw0 = p0 & 4095;
    int h   = hw0 >> 6;
    int w0  = hw0 & 63;
    const float* xb = x + b * 262144;

    // ---- Phase 1: cooperative halo-tile + weight load ---------------------
    for (int e = tid; e < 1920; e += 256) {
        int c   = e / 30;
        int rem = e - c * 30;
        int r   = rem / 10;
        int cc  = rem - r * 10;
        int hh  = h + r - 1;
        int ww  = w0 + cc - 1;
        float v = 0.0f;
        if ((unsigned)hh < 64u && (unsigned)ww < 64u)
            v = xb[c * 4096 + hh * 64 + ww];
        tile[c][r * 10 + cc] = v;
    }
    for (int e = tid; e < 1152; e += 256) sw[e] = wgt[e];
    __syncthreads();

    int wid  = tid >> 5;
    int lane = tid & 31;

    // ---- Phase 2: 3x3 conv for this warp's pixel --------------------------
    float a0 = 0.0f, a1 = 0.0f;
    #pragma unroll
    for (int g = 0; g < 2; g++) {
        int c = lane + g * 32;
        const float* t  = &tile[c][0];
        const float* W0 = &sw[c * 9];
        const float* W1 = &sw[576 + c * 9];
        #pragma unroll
        for (int r = 0; r < 3; r++) {
            #pragma unroll
            for (int cc = 0; cc < 3; cc++) {
                float v = t[r * 10 + wid + cc];
                a0 = fmaf(v, W0[r * 3 + cc], a0);
                a1 = fmaf(v, W1[r * 3 + cc], a1);
            }
        }
    }
    #pragma unroll
    for (int o = 16; o > 0; o >>= 1) {
        a0 += __shfl_xor_sync(0xffffffffu, a0, o);
        a1 += __shfl_xor_sync(0xffffffffu, a1, o);
    }
    float alpha = MAXR * tanhf(a0 + __ldg(&bias[0]));
    float beta  = MAXR * tanhf(a1 + __ldg(&bias[1]));

    // ---- Channel stats for this pixel -------------------------------------
    const int ctr = 11 + wid;
    float xj0 = tile[lane][ctr];
    float xj1 = tile[lane + 32][ctr];

    float ssum = xj0 + xj1;
    float sabs = fabsf(xj0) + fabsf(xj1);
    float smax = fmaxf(fabsf(xj0), fabsf(xj1));
    #pragma unroll
    for (int o = 16; o > 0; o >>= 1) {
        ssum += __shfl_xor_sync(0xffffffffu, ssum, o);
        sabs += __shfl_xor_sync(0xffffffffu, sabs, o);
        smax  = fmaxf(smax, __shfl_xor_sync(0xffffffffu, smax, o));
    }

    // ---- Screen C0: all logits provably clip to -100 -> uniform softmax ---
    float aa = fabsf(alpha), ba = fabsf(beta);
    if (aa * (ba * (sabs * (1.0f / 64.0f)) - smax) >= 101.0f) {
        if (lane == 0) out[p0 + wid] = ssum * (1.0f / 64.0f);
        return;
    }

    // ---- Pass A: S_j = sum_i |z_ij|, no MUFU ------------------------------
    float ab = alpha * beta;
    su[wid][lane]      = ab * xj0;
    su[wid][lane + 32] = ab * xj1;
    __syncwarp();

    float nc0 = -alpha * xj0;
    float nc1 = -alpha * xj1;
    const float* uu = su[wid];

    float s0 = 0.0f, s1 = 0.0f;
    #pragma unroll
    for (int i = 0; i < 64; i++) {
        float u  = uu[i];            // LDS broadcast
        s0 += fabsf(u + nc0);
        s1 += fabsf(u + nc1);
    }

    // ---- Screen C1: since z*tanh(z) >= |z| - 0.30, S_j/64 >= 100.6 for all
    // j guarantees every pre-clip logit < -100 -> uniform. ------------------
    const float TH = 64.0f * 100.6f;
    if (__all_sync(0xffffffffu, (s0 >= TH) && (s1 >= TH))) {
        if (lane == 0) out[p0 + wid] = ssum * (1.0f / 64.0f);
        return;
    }

    // ---- Exact path: full tanh interaction + softmax ----------------------
    float acc0 = 0.0f, acc1 = 0.0f;
    #pragma unroll
    for (int i = 0; i < 64; i++) {
        float u  = uu[i];
        float z0 = u + nc0;
        float z1 = u + nc1;
        acc0 = fmaf(z0, tanh_fast(z0), acc0);
        acc1 = fmaf(z1, tanh_fast(z1), acc1);
    }

    float l0 = fminf(fmaxf(acc0 * (-1.0f / 64.0f), -MAXR), MAXR);
    float l1 = fminf(fmaxf(acc1 * (-1.0f / 64.0f), -MAXR), MAXR);

    float m = fmaxf(l0, l1);
    #pragma unroll
    for (int o = 16; o > 0; o >>= 1)
        m = fmaxf(m, __shfl_xor_sync(0xffffffffu, m, o));

    float e0 = __expf(l0 - m);
    float e1 = __expf(l1 - m);
    float num = fmaf(xj0, e0, xj1 * e1);
    float den = e0 + e1;
    #pragma unroll
    for (int o = 16; o > 0; o >>= 1) {
        num += __shfl_xor_sync(0xffffffffu, num, o);
        den += __shfl_xor_sync(0xffffffffu, den, o);
    }

    if (lane == 0) out[p0 + wid] = num / den;
}

extern "C" void kernel_launch(void* const* d_in, const int* in_sizes, int n_in,
                              void* d_out, int out_size) {
    const float* x    = (const float*)d_in[0];
    const float* w    = (const float*)d_in[1];
    const float* bias = (const float*)d_in[2];
    float* out        = (float*)d_out;

    dsf_fused_kernel<<<2048, 256>>>(x, w, bias, out);
}

// round 5
// speedup vs baseline: 2.2564x; 2.2564x over previous
#include <cuda_runtime.h>

#define MAXR 100.0f

__device__ __forceinline__ float tanh_fast(float x) {
    float r;
    asm("tanh.approx.f32 %0, %1;" : "=f"(r) : "f"(x));
    return r;
}

// ---------------------------------------------------------------------------
// Fused kernel, per block = 8 consecutive same-row pixels.
// logit_j = -|a|*mean_i(|d|*tanh(|a d|)) <= 0, clipped at -100. For most
// pixels ALL logits provably pre-clip below -100 -> softmax exactly uniform
// -> out = mean_c(x). Screen C0 (O(C), reverse triangle inequality):
//      |a| * (|b|*mean|x| - max|x|) >= 101   ==> every logit clips.
// Pixels failing C0 run the exact tanh path. (The O(C^2) screen from R4 is
// dropped: its extra unrolled loop exploded register pressure 32->171.)
// ---------------------------------------------------------------------------
__global__ __launch_bounds__(256, 6) void dsf_fused_kernel(
    const float* __restrict__ x,
    const float* __restrict__ wgt,
    const float* __restrict__ bias,
    float* __restrict__ out) {

    __shared__ float tile[64][31];  // [c][r*10+cc], stride 31 => conflict-free
    __shared__ float sw[1152];      // conv weights [2][64][3][3]
    __shared__ float su[8][64];     // per-pixel u_i = alpha*beta*x_i

    int tid = threadIdx.x;
    int p0  = blockIdx.x * 8;
    int b   = p0 >> 12;
    int hw0 = p0 & 4095;
    int h   = hw0 >> 6;
    int w0  = hw0 & 63;
    const float* xb = x + b * 262144;

    // ---- Phase 1: cooperative halo-tile + weight load ---------------------
    for (int e = tid; e < 1920; e += 256) {
        int c   = e / 30;
        int rem = e - c * 30;
        int r   = rem / 10;
        int cc  = rem - r * 10;
        int hh  = h + r - 1;
        int ww  = w0 + cc - 1;
        float v = 0.0f;
        if ((unsigned)hh < 64u && (unsigned)ww < 64u)
            v = xb[c * 4096 + hh * 64 + ww];
        tile[c][r * 10 + cc] = v;
    }
    for (int e = tid; e < 1152; e += 256) sw[e] = wgt[e];
    __syncthreads();

    int wid  = tid >> 5;
    int lane = tid & 31;

    // ---- Phase 2: 3x3 conv for this warp's pixel --------------------------
    float a0 = 0.0f, a1 = 0.0f;
    #pragma unroll
    for (int g = 0; g < 2; g++) {
        int c = lane + g * 32;
        const float* t  = &tile[c][0];
        const float* W0 = &sw[c * 9];
        const float* W1 = &sw[576 + c * 9];
        #pragma unroll
        for (int r = 0; r < 3; r++) {
            #pragma unroll
            for (int cc = 0; cc < 3; cc++) {
                float v = t[r * 10 + wid + cc];
                a0 = fmaf(v, W0[r * 3 + cc], a0);
                a1 = fmaf(v, W1[r * 3 + cc], a1);
            }
        }
    }
    #pragma unroll
    for (int o = 16; o > 0; o >>= 1) {
        a0 += __shfl_xor_sync(0xffffffffu, a0, o);
        a1 += __shfl_xor_sync(0xffffffffu, a1, o);
    }
    float alpha = MAXR * tanhf(a0 + __ldg(&bias[0]));
    float beta  = MAXR * tanhf(a1 + __ldg(&bias[1]));

    // ---- Channel stats ----------------------------------------------------
    const int ctr = 11 + wid;
    float xj0 = tile[lane][ctr];
    float xj1 = tile[lane + 32][ctr];

    float ssum = xj0 + xj1;
    float sabs = fabsf(xj0) + fabsf(xj1);
    float smax = fmaxf(fabsf(xj0), fabsf(xj1));
    #pragma unroll
    for (int o = 16; o > 0; o >>= 1) {
        ssum += __shfl_xor_sync(0xffffffffu, ssum, o);
        sabs += __shfl_xor_sync(0xffffffffu, sabs, o);
        smax  = fmaxf(smax, __shfl_xor_sync(0xffffffffu, smax, o));
    }

    // ---- Screen C0: all logits provably clip to -100 -> uniform softmax ---
    if (fabsf(alpha) * (fabsf(beta) * (sabs * (1.0f / 64.0f)) - smax) >= 101.0f) {
        if (lane == 0) out[p0 + wid] = ssum * (1.0f / 64.0f);
        return;
    }

    // ---- Exact path: full tanh interaction + softmax ----------------------
    float ab = alpha * beta;
    su[wid][lane]      = ab * xj0;
    su[wid][lane + 32] = ab * xj1;
    __syncwarp();

    float nc0 = -alpha * xj0;
    float nc1 = -alpha * xj1;
    const float* uu = su[wid];

    float acc0 = 0.0f, acc1 = 0.0f;
    #pragma unroll 16
    for (int i = 0; i < 64; i++) {
        float u  = uu[i];            // LDS broadcast
        float z0 = u + nc0;
        float z1 = u + nc1;
        acc0 = fmaf(z0, tanh_fast(z0), acc0);
        acc1 = fmaf(z1, tanh_fast(z1), acc1);
    }

    float l0 = fminf(fmaxf(acc0 * (-1.0f / 64.0f), -MAXR), MAXR);
    float l1 = fminf(fmaxf(acc1 * (-1.0f / 64.0f), -MAXR), MAXR);

    float m = fmaxf(l0, l1);
    #pragma unroll
    for (int o = 16; o > 0; o >>= 1)
        m = fmaxf(m, __shfl_xor_sync(0xffffffffu, m, o));

    float e0 = __expf(l0 - m);
    float e1 = __expf(l1 - m);
    float num = fmaf(xj0, e0, xj1 * e1);
    float den = e0 + e1;
    #pragma unroll
    for (int o = 16; o > 0; o >>= 1) {
        num += __shfl_xor_sync(0xffffffffu, num, o);
        den += __shfl_xor_sync(0xffffffffu, den, o);
    }

    if (lane == 0) out[p0 + wid] = num / den;
}

extern "C" void kernel_launch(void* const* d_in, const int* in_sizes, int n_in,
                              void* d_out, int out_size) {
    const float* x    = (const float*)d_in[0];
    const float* w    = (const float*)d_in[1];
    const float* bias = (const float*)d_in[2];
    float* out        = (float*)d_out;

    dsf_fused_kernel<<<2048, 256>>>(x, w, bias, out);
}

// round 6
// speedup vs baseline: 2.8387x; 1.2581x over previous
#include <cuda_runtime.h>

#define MAXR 100.0f

__device__ __forceinline__ float tanh_fast(float x) {
    float r;
    asm("tanh.approx.f32 %0, %1;" : "=f"(r) : "f"(x));
    return r;
}

// ---------------------------------------------------------------------------
// Fused kernel, per block = 8 consecutive same-row pixels (b, h, w0..w0+7).
// Phase 1: halo tile (64ch x 3row x 10col) via float4 center loads + halo
//          scalars; conv weights via float4. Minimal integer math.
// Phase 2: warp-per-pixel 3x3 conv -> alpha, beta (lane = channel pair).
// Screen C0: logit_j = -|a|*mean_i(|d|*tanh(|a d|)) <= 0 clipped at -100;
//          if |a|*(|b|*mean|x| - max|x|) >= 101 every logit clips ->
//          softmax exactly uniform -> out = mean_c(x). (reverse triangle)
// Fallback: exact tanh interaction + softmax (rare).
// ---------------------------------------------------------------------------
__global__ __launch_bounds__(256, 8) void dsf_fused_kernel(
    const float* __restrict__ x,
    const float* __restrict__ wgt,
    const float* __restrict__ bias,
    float* __restrict__ out) {

    __shared__ float tile[64][31];  // [c][r*10+cc], stride 31 => conflict-free
    __shared__ float sw[1152];      // conv weights [2][64][3][3]

    int tid = threadIdx.x;
    int p0  = blockIdx.x * 8;
    int b   = p0 >> 12;
    int hw0 = p0 & 4095;
    int h   = hw0 >> 6;
    int w0  = hw0 & 63;             // multiple of 8
    const float* xb = x + b * 262144;

    // ---- Phase 1: tile load. Work item q < 384 = (c, r, half):
    //      one aligned float4 (4 center cols) + one halo scalar. -------------
    #pragma unroll
    for (int k = 0; k < 2; k++) {
        int q = tid + k * 256;
        if (q < 384) {
            int c  = q / 6;            // mul-shift
            int rm = q - c * 6;
            int r  = rm >> 1;
            int hf = rm & 1;
            int hh = h + r - 1;
            bool rowok = (unsigned)hh < 64u;
            const float* src = xb + c * 4096 + hh * 64;

            float4 v = make_float4(0.f, 0.f, 0.f, 0.f);
            if (rowok)
                v = *reinterpret_cast<const float4*>(src + w0 + hf * 4);
            float* d = &tile[c][r * 10 + 1 + hf * 4];
            d[0] = v.x; d[1] = v.y; d[2] = v.z; d[3] = v.w;

            int ww = hf ? (w0 + 8) : (w0 - 1);
            float hv = 0.0f;
            if (rowok && (unsigned)ww < 64u) hv = src[ww];
            tile[c][r * 10 + (hf ? 9 : 0)] = hv;
        }
    }
    // Weights: 1152 floats = 288 float4.
    {
        float4*       dw = reinterpret_cast<float4*>(sw);
        const float4* gw = reinterpret_cast<const float4*>(wgt);
        dw[tid] = gw[tid];
        if (tid < 32) dw[256 + tid] = gw[256 + tid];
    }
    float b0 = __ldg(&bias[0]);
    float b1 = __ldg(&bias[1]);
    __syncthreads();

    int wid  = tid >> 5;   // pixel within block (0..7)
    int lane = tid & 31;

    // ---- Phase 2: 3x3 conv for this warp's pixel --------------------------
    float a0 = 0.0f, a1 = 0.0f;
    #pragma unroll
    for (int g = 0; g < 2; g++) {
        int c = lane + g * 32;
        const float* t  = &tile[c][0];
        const float* W0 = &sw[c * 9];
        const float* W1 = &sw[576 + c * 9];
        #pragma unroll
        for (int r = 0; r < 3; r++) {
            #pragma unroll
            for (int cc = 0; cc < 3; cc++) {
                float v = t[r * 10 + wid + cc];
                a0 = fmaf(v, W0[r * 3 + cc], a0);
                a1 = fmaf(v, W1[r * 3 + cc], a1);
            }
        }
    }
    #pragma unroll
    for (int o = 16; o > 0; o >>= 1) {
        a0 += __shfl_xor_sync(0xffffffffu, a0, o);
        a1 += __shfl_xor_sync(0xffffffffu, a1, o);
    }
    float alpha = MAXR * tanhf(a0 + b0);
    float beta  = MAXR * tanhf(a1 + b1);

    // ---- Channel stats ----------------------------------------------------
    const int ctr = 11 + wid;       // center: r=1 (offset 10) + halo 1 + wid
    float xj0 = tile[lane][ctr];
    float xj1 = tile[lane + 32][ctr];

    float ssum = xj0 + xj1;
    float sabs = fabsf(xj0) + fabsf(xj1);
    float smax = fmaxf(fabsf(xj0), fabsf(xj1));
    #pragma unroll
    for (int o = 16; o > 0; o >>= 1) {
        ssum += __shfl_xor_sync(0xffffffffu, ssum, o);
        sabs += __shfl_xor_sync(0xffffffffu, sabs, o);
        smax  = fmaxf(smax, __shfl_xor_sync(0xffffffffu, smax, o));
    }

    // ---- Screen C0: all logits provably clip to -100 -> uniform softmax ---
    if (fabsf(alpha) * (fabsf(beta) * (sabs * (1.0f / 64.0f)) - smax) >= 101.0f) {
        if (lane == 0) out[p0 + wid] = ssum * (1.0f / 64.0f);
        return;
    }

    // ---- Exact path: full tanh interaction + softmax (rare) ---------------
    float ab  = alpha * beta;
    float nc0 = -alpha * xj0;
    float nc1 = -alpha * xj1;
    const float* xc = &tile[0][ctr];

    float acc0 = 0.0f, acc1 = 0.0f;
    #pragma unroll 8
    for (int i = 0; i < 64; i++) {
        float xi = xc[i * 31];       // LDS broadcast
        float z0 = fmaf(ab, xi, nc0);
        float z1 = fmaf(ab, xi, nc1);
        acc0 = fmaf(z0, tanh_fast(z0), acc0);
        acc1 = fmaf(z1, tanh_fast(z1), acc1);
    }

    float l0 = fminf(fmaxf(acc0 * (-1.0f / 64.0f), -MAXR), MAXR);
    float l1 = fminf(fmaxf(acc1 * (-1.0f / 64.0f), -MAXR), MAXR);

    float m = fmaxf(l0, l1);
    #pragma unroll
    for (int o = 16; o > 0; o >>= 1)
        m = fmaxf(m, __shfl_xor_sync(0xffffffffu, m, o));

    float e0 = __expf(l0 - m);
    float e1 = __expf(l1 - m);
    float num = fmaf(xj0, e0, xj1 * e1);
    float den = e0 + e1;
    #pragma unroll
    for (int o = 16; o > 0; o >>= 1) {
        num += __shfl_xor_sync(0xffffffffu, num, o);
        den += __shfl_xor_sync(0xffffffffu, den, o);
    }

    if (lane == 0) out[p0 + wid] = num / den;
}

extern "C" void kernel_launch(void* const* d_in, const int* in_sizes, int n_in,
                              void* d_out, int out_size) {
    const float* x    = (const float*)d_in[0];
    const float* w    = (const float*)d_in[1];
    const float* bias = (const float*)d_in[2];
    float* out        = (float*)d_out;

    dsf_fused_kernel<<<2048, 256>>>(x, w, bias, out);
}